// round 14
// baseline (speedup 1.0000x reference)
#include <cuda_runtime.h>
#include <math.h>

static constexpr int NE = 8;
static constexpr int NT = 256;
static constexpr int ND = 2048;
static constexpr int NH = 8192;

// Scratch (__device__ globals: allocation-guard safe)
__device__ float g_s1[(size_t)NE * NT * NH];   // h1 / mid (64MB)
__device__ float g_s2[(size_t)NE * NT * ND];   // tf32-rounded x (16MB)

__device__ __forceinline__ unsigned f2tf(float x) {
    unsigned r;
    asm("cvt.rna.tf32.f32 %0, %1;" : "=r"(r) : "f"(x));
    return r;
}

__device__ __forceinline__ float silu(float x) {
    return x / (1.0f + __expf(-x));
}

__device__ __forceinline__ unsigned s2u(const void* p) {
    unsigned a;
    asm("{ .reg .u64 t; cvta.to.shared.u64 t, %1; cvt.u32.u64 %0, t; }" : "=r"(a) : "l"(p));
    return a;
}

__device__ __forceinline__ void cpasync16(unsigned dst, const void* src) {
    asm volatile("cp.async.cg.shared.global [%0], [%1], 16;" :: "r"(dst), "l"(src) : "memory");
}

#define MMA_TF32(ACC, A0, A1, A2, A3, B0, B1)                                  \
    asm volatile(                                                              \
        "mma.sync.aligned.m16n8k8.row.col.f32.tf32.tf32.f32 "                  \
        "{%0,%1,%2,%3}, {%4,%5,%6,%7}, {%8,%9}, {%0,%1,%2,%3};"                \
        : "+f"((ACC)[0]), "+f"((ACC)[1]), "+f"((ACC)[2]), "+f"((ACC)[3])       \
        : "r"(A0), "r"(A1), "r"(A2), "r"(A3), "r"(B0), "r"(B1))

// Elementwise tf32 pre-round (x -> g_s2)
__global__ void round_tf32(const float* __restrict__ in, float* __restrict__ out, int n4) {
    int i = blockIdx.x * blockDim.x + threadIdx.x;
    if (i < n4) {
        float4 v = ((const float4*)in)[i];
        float4 w;
        w.x = __uint_as_float(f2tf(v.x));
        w.y = __uint_as_float(f2tf(v.y));
        w.z = __uint_as_float(f2tf(v.z));
        w.w = __uint_as_float(f2tf(v.w));
        ((float4*)out)[i] = w;
    }
}

// k-permutation (both kernels): within each 8-wide MMA k-group, physical A slot
// tig carries logical k8+2*tig and slot tig+4 carries k8+2*tig+1; B supplies the
// same logical k in the matching physical slots. Sum over k unchanged.

// ---------------------------------------------------------------------------
// Up/gate GEMM: C[NT,NH] = A[NT,ND] @ B[ND,NH]   (B n-contiguous)
// SA=40 (LDS.64 A frags), SB=132 (permuted-row LDS.32 B frags, banks 8tig+g).
// 2-stage cp.async with dual-sync (the gemm_down-proven pipeline shape):
// stage = 37.4KB, 2 stages = 74.8KB/CTA -> 2 CTA/SM guaranteed.
// EPI 0: C = acc      EPI 1: C = round(silu(Saux) * acc)
// ---------------------------------------------------------------------------
template<int EPI>
__global__ __launch_bounds__(256, 2)
void gemm_upgate(const float* __restrict__ A, const float* __restrict__ Bg,
                 const float* __restrict__ Saux, float* __restrict__ Cg)
{
    constexpr int SA = 40;            // frag banks 8g+2tig -> LDS.64 conflict-free
    constexpr int SB = 132;           // frag banks 8tig+g (+4) -> LDS.32 conflict-free
    constexpr int ASZ = 128 * SA;
    constexpr int BSZ = 32 * SB;      // staging max offset = 31*132+128 = 4224 = BSZ
    constexpr int STG = ASZ + BSZ;

    extern __shared__ float sm[];
    const unsigned sbase = s2u(sm);

    const int tid  = threadIdx.x;
    const int wid  = tid >> 5;
    const int lane = tid & 31;
    const int wm   = wid >> 2;
    const int wn   = wid & 3;
    const int g    = lane >> 2;
    const int tig  = lane & 3;

    const int m0 = blockIdx.y * 128;
    const int n0 = blockIdx.x * 128;
    const size_t z = blockIdx.z;

    const float* Ae = A  + z * (size_t)NT * ND + (size_t)m0 * ND;
    const float* Be = Bg + z * (size_t)ND * NH;
    float*       Ce = Cg + z * (size_t)NT * NH;
    const float* Se = Saux + z * (size_t)NT * NH;

    float acc[4][4][4];
    #pragma unroll
    for (int i = 0; i < 4; i++)
        #pragma unroll
        for (int j = 0; j < 4; j++)
            #pragma unroll
            for (int k = 0; k < 4; k++)
                acc[i][j][k] = 0.0f;

    auto stage = [&](int s, int kt) {
        const unsigned ab = sbase + (unsigned)s * STG * 4;
        const unsigned bb = ab + ASZ * 4;
        #pragma unroll
        for (int i = 0; i < 4; i++) {
            int idx = tid + i * 256;
            int r = idx >> 3, c = (idx & 7) * 4;
            cpasync16(ab + (r * SA + c) * 4, Ae + (size_t)r * ND + kt + c);
        }
        #pragma unroll
        for (int i = 0; i < 4; i++) {
            int idx = tid + i * 256;
            int kr = idx >> 5, nc = (idx & 31) * 4;
            cpasync16(bb + (kr * SB + nc) * 4, Be + (size_t)(kt + kr) * NH + n0 + nc);
        }
        asm volatile("cp.async.commit_group;" ::: "memory");
    };

    constexpr int NIT = ND / 32;      // 64
    stage(0, 0);
    stage(1, 32);

    #pragma unroll 1
    for (int it = 0; it < NIT; it++) {
        if (it + 1 < NIT) asm volatile("cp.async.wait_group 1;" ::: "memory");
        else              asm volatile("cp.async.wait_group 0;" ::: "memory");
        __syncthreads();

        const float* As = sm + (size_t)(it & 1) * STG;
        const float* Bs = As + ASZ;

        #pragma unroll
        for (int ks = 0; ks < 4; ks++) {
            const int kk = ks * 8 + 2 * tig;

            float2 a[4][2];
            #pragma unroll
            for (int mi = 0; mi < 4; mi++) {
                int row = wm * 64 + mi * 16 + g;
                a[mi][0] = *(const float2*)&As[row       * SA + kk];
                a[mi][1] = *(const float2*)&As[(row + 8) * SA + kk];
            }
            unsigned bf[4][2];
            #pragma unroll
            for (int nj = 0; nj < 4; nj++) {
                int n = wn * 32 + nj * 8 + g;
                bf[nj][0] = f2tf(Bs[kk       * SB + n]);
                bf[nj][1] = f2tf(Bs[(kk + 1) * SB + n]);
            }
            #pragma unroll
            for (int mi = 0; mi < 4; mi++) {
                unsigned a0 = __float_as_uint(a[mi][0].x);
                unsigned a1 = __float_as_uint(a[mi][1].x);
                unsigned a2 = __float_as_uint(a[mi][0].y);
                unsigned a3 = __float_as_uint(a[mi][1].y);
                #pragma unroll
                for (int nj = 0; nj < 4; nj++)
                    MMA_TF32(acc[mi][nj], a0, a1, a2, a3, bf[nj][0], bf[nj][1]);
            }
        }

        if (it + 2 < NIT) {
            __syncthreads();                  // buffer it&1 fully consumed
            stage(it & 1, (it + 2) * 32);
        }
    }

    #pragma unroll
    for (int mi = 0; mi < 4; mi++) {
        #pragma unroll
        for (int nj = 0; nj < 4; nj++) {
            int row = m0 + wm * 64 + mi * 16 + g;
            int col = n0 + wn * 32 + nj * 8 + 2 * tig;
            size_t i00 = (size_t)row * NH + col;
            size_t i10 = (size_t)(row + 8) * NH + col;
            float2 v0, v1;
            if (EPI == 0) {
                v0.x = acc[mi][nj][0]; v0.y = acc[mi][nj][1];
                v1.x = acc[mi][nj][2]; v1.y = acc[mi][nj][3];
            } else {
                float2 h0 = *(const float2*)&Se[i00];
                float2 h1 = *(const float2*)&Se[i10];
                // store mid tf32-rounded so gemm_down's A needs no cvt
                v0.x = __uint_as_float(f2tf(silu(h0.x) * acc[mi][nj][0]));
                v0.y = __uint_as_float(f2tf(silu(h0.y) * acc[mi][nj][1]));
                v1.x = __uint_as_float(f2tf(silu(h1.x) * acc[mi][nj][2]));
                v1.y = __uint_as_float(f2tf(silu(h1.y) * acc[mi][nj][3]));
            }
            *(float2*)&Ce[i00] = v0;
            *(float2*)&Ce[i10] = v1;
        }
    }
}

// ---------------------------------------------------------------------------
// Down proj (R12/R13-measured layout, unchanged): out[T,D] = mid[T,H] @ w2^T.
// A pre-rounded; B k-contiguous. SA=SB=40, LDS.64 both operands via the
// k-permutation. CTA 128x128, 2-stage cp.async.
// ---------------------------------------------------------------------------
__global__ __launch_bounds__(256, 2)
void gemm_down(const float* __restrict__ A, const float* __restrict__ Bg,
               float* __restrict__ Cg)
{
    constexpr int SA = 40;
    constexpr int SB = 40;            // banks 8g+2tig -> LDS.64 conflict-free
    constexpr int ASZ = 128 * SA;
    constexpr int BSZ = 128 * SB;
    constexpr int STG = ASZ + BSZ;

    extern __shared__ float sm[];
    const unsigned sbase = s2u(sm);

    const int tid  = threadIdx.x;
    const int wid  = tid >> 5;
    const int lane = tid & 31;
    const int wm   = wid >> 2;
    const int wn   = wid & 3;
    const int g    = lane >> 2;
    const int tig  = lane & 3;

    const int m0 = blockIdx.y * 128;
    const int n0 = blockIdx.x * 128;
    const size_t z = blockIdx.z;

    const float* Ae = A  + z * (size_t)NT * NH + (size_t)m0 * NH;
    const float* Be = Bg + z * (size_t)ND * NH;
    float*       Ce = Cg + z * (size_t)NT * ND;

    float acc[4][4][4];
    #pragma unroll
    for (int i = 0; i < 4; i++)
        #pragma unroll
        for (int j = 0; j < 4; j++)
            #pragma unroll
            for (int k = 0; k < 4; k++)
                acc[i][j][k] = 0.0f;

    auto stage = [&](int s, int kt) {
        const unsigned ab = sbase + (unsigned)s * STG * 4;
        const unsigned bb = ab + ASZ * 4;
        #pragma unroll
        for (int i = 0; i < 4; i++) {
            int idx = tid + i * 256;
            int r = idx >> 3, c = (idx & 7) * 4;
            cpasync16(ab + (r * SA + c) * 4, Ae + (size_t)r * NH + kt + c);
        }
        #pragma unroll
        for (int i = 0; i < 4; i++) {
            int idx = tid + i * 256;
            int nr = idx >> 3, kc = (idx & 7) * 4;
            cpasync16(bb + (nr * SB + kc) * 4, Be + (size_t)(n0 + nr) * NH + kt + kc);
        }
        asm volatile("cp.async.commit_group;" ::: "memory");
    };

    constexpr int NIT = NH / 32;      // 256
    stage(0, 0);
    stage(1, 32);

    #pragma unroll 1
    for (int it = 0; it < NIT; it++) {
        if (it + 1 < NIT) asm volatile("cp.async.wait_group 1;" ::: "memory");
        else              asm volatile("cp.async.wait_group 0;" ::: "memory");
        __syncthreads();

        const float* As = sm + (size_t)(it & 1) * STG;
        const float* Bs = As + ASZ;

        #pragma unroll
        for (int ks = 0; ks < 4; ks++) {
            const int kk = ks * 8 + 2 * tig;

            float2 a[4][2];
            #pragma unroll
            for (int mi = 0; mi < 4; mi++) {
                int row = wm * 64 + mi * 16 + g;
                a[mi][0] = *(const float2*)&As[row       * SA + kk];
                a[mi][1] = *(const float2*)&As[(row + 8) * SA + kk];
            }
            unsigned bf[4][2];
            #pragma unroll
            for (int nj = 0; nj < 4; nj++) {
                int n = wn * 32 + nj * 8 + g;
                float2 bp = *(const float2*)&Bs[n * SB + kk];
                bf[nj][0] = f2tf(bp.x);
                bf[nj][1] = f2tf(bp.y);
            }
            #pragma unroll
            for (int mi = 0; mi < 4; mi++) {
                unsigned a0 = __float_as_uint(a[mi][0].x);
                unsigned a1 = __float_as_uint(a[mi][1].x);
                unsigned a2 = __float_as_uint(a[mi][0].y);
                unsigned a3 = __float_as_uint(a[mi][1].y);
                #pragma unroll
                for (int nj = 0; nj < 4; nj++)
                    MMA_TF32(acc[mi][nj], a0, a1, a2, a3, bf[nj][0], bf[nj][1]);
            }
        }

        if (it + 2 < NIT) {
            __syncthreads();                  // buffer it&1 fully consumed
            stage(it & 1, (it + 2) * 32);
        }
    }

    #pragma unroll
    for (int mi = 0; mi < 4; mi++) {
        #pragma unroll
        for (int nj = 0; nj < 4; nj++) {
            int row = m0 + wm * 64 + mi * 16 + g;
            int col = n0 + wn * 32 + nj * 8 + 2 * tig;
            float2 v0, v1;
            v0.x = acc[mi][nj][0]; v0.y = acc[mi][nj][1];
            v1.x = acc[mi][nj][2]; v1.y = acc[mi][nj][3];
            *(float2*)&Ce[(size_t)row * ND + col]       = v0;
            *(float2*)&Ce[(size_t)(row + 8) * ND + col] = v1;
        }
    }
}

extern "C" void kernel_launch(void* const* d_in, const int* in_sizes, int n_in,
                              void* d_out, int out_size)
{
    const float* x  = (const float*)d_in[0];
    const float* w1 = (const float*)d_in[1];
    const float* w2 = (const float*)d_in[2];
    const float* w3 = (const float*)d_in[3];
    float* out = (float*)d_out;

    float* s1 = nullptr;
    float* s2 = nullptr;
    cudaGetSymbolAddress((void**)&s1, g_s1);   // no allocation; capture-safe
    cudaGetSymbolAddress((void**)&s2, g_s2);

    constexpr size_t SMU = 2 * (size_t)(128 * 40 + 32 * 132) * sizeof(float);  // 74752
    constexpr size_t SMD = 2 * (size_t)(128 * 40 + 128 * 40) * sizeof(float);  // 81920
    cudaFuncSetAttribute(gemm_upgate<0>, cudaFuncAttributeMaxDynamicSharedMemorySize, SMU);
    cudaFuncSetAttribute(gemm_upgate<1>, cudaFuncAttributeMaxDynamicSharedMemorySize, SMU);
    cudaFuncSetAttribute(gemm_down,      cudaFuncAttributeMaxDynamicSharedMemorySize, SMD);

    dim3 blk(256);
    dim3 g0(NH / 128, NT / 128, NE);   // (64, 2, 8)
    dim3 g1(ND / 128, NT / 128, NE);   // (16, 2, 8)

    // 0) pre-round x to tf32 (A operand of GEMM1/2)
    int n4 = NE * NT * ND / 4;
    round_tf32<<<(n4 + 255) / 256, 256>>>(x, s2, n4);

    // 1) h1 = x @ w1                       -> s1
    gemm_upgate<0><<<g0, blk, SMU>>>(s2, w1, s1, s1);
    // 2) mid = round(silu(h1) * (x @ w3))  -> s1 (in place)
    gemm_upgate<1><<<g0, blk, SMU>>>(s2, w3, s1, s1);
    // 3) out = mid @ w2^T
    gemm_down<<<g1, blk, SMD>>>(s1, w2, out);
}

// round 15
// speedup vs baseline: 1.1006x; 1.1006x over previous
#include <cuda_runtime.h>
#include <math.h>

static constexpr int NE = 8;
static constexpr int NT = 256;
static constexpr int ND = 2048;
static constexpr int NH = 8192;

// Scratch (__device__ globals: allocation-guard safe)
__device__ float g_s1[(size_t)NE * NT * NH];   // h1 / mid (64MB)
__device__ float g_s2[(size_t)NE * NT * ND];   // tf32-rounded x (16MB)

__device__ __forceinline__ unsigned f2tf(float x) {
    unsigned r;
    asm("cvt.rna.tf32.f32 %0, %1;" : "=r"(r) : "f"(x));
    return r;
}

__device__ __forceinline__ float silu(float x) {
    return x / (1.0f + __expf(-x));
}

__device__ __forceinline__ unsigned s2u(const void* p) {
    unsigned a;
    asm("{ .reg .u64 t; cvta.to.shared.u64 t, %1; cvt.u32.u64 %0, t; }" : "=r"(a) : "l"(p));
    return a;
}

__device__ __forceinline__ void cpasync16(unsigned dst, const void* src) {
    asm volatile("cp.async.cg.shared.global [%0], [%1], 16;" :: "r"(dst), "l"(src) : "memory");
}

#define MMA_TF32(ACC, A0, A1, A2, A3, B0, B1)                                  \
    asm volatile(                                                              \
        "mma.sync.aligned.m16n8k8.row.col.f32.tf32.tf32.f32 "                  \
        "{%0,%1,%2,%3}, {%4,%5,%6,%7}, {%8,%9}, {%0,%1,%2,%3};"                \
        : "+f"((ACC)[0]), "+f"((ACC)[1]), "+f"((ACC)[2]), "+f"((ACC)[3])       \
        : "r"(A0), "r"(A1), "r"(A2), "r"(A3), "r"(B0), "r"(B1))

// Elementwise tf32 pre-round (x -> g_s2)
__global__ void round_tf32(const float* __restrict__ in, float* __restrict__ out, int n4) {
    int i = blockIdx.x * blockDim.x + threadIdx.x;
    if (i < n4) {
        float4 v = ((const float4*)in)[i];
        float4 w;
        w.x = __uint_as_float(f2tf(v.x));
        w.y = __uint_as_float(f2tf(v.y));
        w.z = __uint_as_float(f2tf(v.z));
        w.w = __uint_as_float(f2tf(v.w));
        ((float4*)out)[i] = w;
    }
}

// ---------------------------------------------------------------------------
// Up/gate GEMM: C[NT,NH] = A[NT,ND] @ B[ND,NH]   (B n-contiguous)
// 128 threads = 4 warps in 2x2, warp tile 64x64, CTA tile 128x128.
// Memory scheme = R8-measured-best: SA=36 / SB=136, LDS.32 fragments,
// 3-stage cp.async, 1 barrier per k-iter.
// EPI 0: C = acc      EPI 1: C = round(silu(Saux) * acc)
// ---------------------------------------------------------------------------
template<int EPI>
__global__ __launch_bounds__(128, 2)
void gemm_upgate(const float* __restrict__ A, const float* __restrict__ Bg,
                 const float* __restrict__ Saux, float* __restrict__ Cg)
{
    constexpr int SA = 36;            // frag bank 4g+tig -> conflict-free
    constexpr int SB = 136;           // frag bank 8tig+g -> conflict-free
    constexpr int ASZ = 128 * SA;
    constexpr int BSZ = 32 * SB;
    constexpr int STG = ASZ + BSZ;

    extern __shared__ float sm[];
    const unsigned sbase = s2u(sm);

    const int tid  = threadIdx.x;
    const int wid  = tid >> 5;
    const int lane = tid & 31;
    const int wm   = wid >> 1;       // 0..1 (64 rows each)
    const int wn   = wid & 1;        // 0..1 (64 cols each)
    const int g    = lane >> 2;
    const int tig  = lane & 3;

    const int m0 = blockIdx.y * 128;
    const int n0 = blockIdx.x * 128;
    const size_t z = blockIdx.z;

    const float* Ae = A  + z * (size_t)NT * ND + (size_t)m0 * ND;
    const float* Be = Bg + z * (size_t)ND * NH;
    float*       Ce = Cg + z * (size_t)NT * NH;
    const float* Se = Saux + z * (size_t)NT * NH;

    float acc[4][8][4];
    #pragma unroll
    for (int i = 0; i < 4; i++)
        #pragma unroll
        for (int j = 0; j < 8; j++)
            #pragma unroll
            for (int k = 0; k < 4; k++)
                acc[i][j][k] = 0.0f;

    auto stage = [&](int s, int kt) {
        const unsigned ab = sbase + (unsigned)s * STG * 4;
        const unsigned bb = ab + ASZ * 4;
        #pragma unroll
        for (int i = 0; i < 8; i++) {
            int idx = tid + i * 128;
            int r = idx >> 3, c = (idx & 7) * 4;
            cpasync16(ab + (r * SA + c) * 4, Ae + (size_t)r * ND + kt + c);
        }
        #pragma unroll
        for (int i = 0; i < 8; i++) {
            int idx = tid + i * 128;
            int kr = idx >> 5, nc = (idx & 31) * 4;
            cpasync16(bb + (kr * SB + nc) * 4, Be + (size_t)(kt + kr) * NH + n0 + nc);
        }
        asm volatile("cp.async.commit_group;" ::: "memory");
    };

    constexpr int NIT = ND / 32;      // 64
    stage(0, 0);
    stage(1, 32);

    #pragma unroll 1
    for (int it = 0; it < NIT; it++) {
        if (it + 1 < NIT) asm volatile("cp.async.wait_group 1;" ::: "memory");
        else              asm volatile("cp.async.wait_group 0;" ::: "memory");
        __syncthreads();
        if (it + 2 < NIT) stage((it + 2) % 3, (it + 2) * 32);

        const float* As = sm + (size_t)(it % 3) * STG;
        const float* Bs = As + ASZ;

        #pragma unroll
        for (int ks = 0; ks < 4; ks++) {
            const int k8 = ks * 8;

            unsigned af[4][4];
            #pragma unroll
            for (int mi = 0; mi < 4; mi++) {
                int row = wm * 64 + mi * 16 + g;
                af[mi][0] = __float_as_uint(As[row       * SA + k8 + tig]);
                af[mi][1] = __float_as_uint(As[(row + 8) * SA + k8 + tig]);
                af[mi][2] = __float_as_uint(As[row       * SA + k8 + tig + 4]);
                af[mi][3] = __float_as_uint(As[(row + 8) * SA + k8 + tig + 4]);
            }
            unsigned bf[8][2];
            #pragma unroll
            for (int nj = 0; nj < 8; nj++) {
                int n = wn * 64 + nj * 8 + g;
                bf[nj][0] = f2tf(Bs[(k8 + tig)     * SB + n]);
                bf[nj][1] = f2tf(Bs[(k8 + tig + 4) * SB + n]);
            }
            #pragma unroll
            for (int mi = 0; mi < 4; mi++) {
                #pragma unroll
                for (int nj = 0; nj < 8; nj++)
                    MMA_TF32(acc[mi][nj], af[mi][0], af[mi][1], af[mi][2], af[mi][3],
                             bf[nj][0], bf[nj][1]);
            }
        }
    }

    #pragma unroll
    for (int mi = 0; mi < 4; mi++) {
        #pragma unroll
        for (int nj = 0; nj < 8; nj++) {
            int row = m0 + wm * 64 + mi * 16 + g;
            int col = n0 + wn * 64 + nj * 8 + tig * 2;
            size_t i00 = (size_t)row * NH + col;
            size_t i10 = (size_t)(row + 8) * NH + col;
            float2 v0, v1;
            if (EPI == 0) {
                v0.x = acc[mi][nj][0]; v0.y = acc[mi][nj][1];
                v1.x = acc[mi][nj][2]; v1.y = acc[mi][nj][3];
            } else {
                float2 h0 = *(const float2*)&Se[i00];
                float2 h1 = *(const float2*)&Se[i10];
                // store mid tf32-rounded so gemm_down's A needs no cvt
                v0.x = __uint_as_float(f2tf(silu(h0.x) * acc[mi][nj][0]));
                v0.y = __uint_as_float(f2tf(silu(h0.y) * acc[mi][nj][1]));
                v1.x = __uint_as_float(f2tf(silu(h1.x) * acc[mi][nj][2]));
                v1.y = __uint_as_float(f2tf(silu(h1.y) * acc[mi][nj][3]));
            }
            *(float2*)&Ce[i00] = v0;
            *(float2*)&Ce[i10] = v1;
        }
    }
}

// ---------------------------------------------------------------------------
// Down proj: out[T,D] = mid[T,H] @ w2[D,H]^T.  A pre-rounded; B k-contiguous.
// 128 threads = 4 warps in 2x2, warp tile 64x64, CTA tile 128x128.
// Memory scheme = R12-measured-best: SA=SB=40, LDS.64 both operands via
// k-permutation (physical slot tig <- logical k8+2tig, slot tig+4 <- k8+2tig+1,
// same bijection on A and B -> sum over k unchanged). 2-stage cp.async.
// ---------------------------------------------------------------------------
__global__ __launch_bounds__(128, 2)
void gemm_down(const float* __restrict__ A, const float* __restrict__ Bg,
               float* __restrict__ Cg)
{
    constexpr int SA = 40;
    constexpr int SB = 40;            // banks 8g+2tig -> LDS.64 conflict-free
    constexpr int ASZ = 128 * SA;
    constexpr int BSZ = 128 * SB;
    constexpr int STG = ASZ + BSZ;

    extern __shared__ float sm[];
    const unsigned sbase = s2u(sm);

    const int tid  = threadIdx.x;
    const int wid  = tid >> 5;
    const int lane = tid & 31;
    const int wm   = wid >> 1;
    const int wn   = wid & 1;
    const int g    = lane >> 2;
    const int tig  = lane & 3;

    const int m0 = blockIdx.y * 128;
    const int n0 = blockIdx.x * 128;
    const size_t z = blockIdx.z;

    const float* Ae = A  + z * (size_t)NT * NH + (size_t)m0 * NH;
    const float* Be = Bg + z * (size_t)ND * NH;
    float*       Ce = Cg + z * (size_t)NT * ND;

    float acc[4][8][4];
    #pragma unroll
    for (int i = 0; i < 4; i++)
        #pragma unroll
        for (int j = 0; j < 8; j++)
            #pragma unroll
            for (int k = 0; k < 4; k++)
                acc[i][j][k] = 0.0f;

    auto stage = [&](int s, int kt) {
        const unsigned ab = sbase + (unsigned)s * STG * 4;
        const unsigned bb = ab + ASZ * 4;
        #pragma unroll
        for (int i = 0; i < 8; i++) {
            int idx = tid + i * 128;
            int r = idx >> 3, c = (idx & 7) * 4;
            cpasync16(ab + (r * SA + c) * 4, Ae + (size_t)r * NH + kt + c);
        }
        #pragma unroll
        for (int i = 0; i < 8; i++) {
            int idx = tid + i * 128;
            int nr = idx >> 3, kc = (idx & 7) * 4;
            cpasync16(bb + (nr * SB + kc) * 4, Be + (size_t)(n0 + nr) * NH + kt + kc);
        }
        asm volatile("cp.async.commit_group;" ::: "memory");
    };

    constexpr int NIT = NH / 32;      // 256
    stage(0, 0);
    stage(1, 32);

    #pragma unroll 1
    for (int it = 0; it < NIT; it++) {
        if (it + 1 < NIT) asm volatile("cp.async.wait_group 1;" ::: "memory");
        else              asm volatile("cp.async.wait_group 0;" ::: "memory");
        __syncthreads();

        const float* As = sm + (size_t)(it & 1) * STG;
        const float* Bs = As + ASZ;

        #pragma unroll
        for (int ks = 0; ks < 4; ks++) {
            const int kk = ks * 8 + 2 * tig;

            float2 a[4][2];
            #pragma unroll
            for (int mi = 0; mi < 4; mi++) {
                int row = wm * 64 + mi * 16 + g;
                a[mi][0] = *(const float2*)&As[row       * SA + kk];
                a[mi][1] = *(const float2*)&As[(row + 8) * SA + kk];
            }
            unsigned bf[8][2];
            #pragma unroll
            for (int nj = 0; nj < 8; nj++) {
                int n = wn * 64 + nj * 8 + g;
                float2 bp = *(const float2*)&Bs[n * SB + kk];
                bf[nj][0] = f2tf(bp.x);
                bf[nj][1] = f2tf(bp.y);
            }
            #pragma unroll
            for (int mi = 0; mi < 4; mi++) {
                unsigned a0 = __float_as_uint(a[mi][0].x);
                unsigned a1 = __float_as_uint(a[mi][1].x);
                unsigned a2 = __float_as_uint(a[mi][0].y);
                unsigned a3 = __float_as_uint(a[mi][1].y);
                #pragma unroll
                for (int nj = 0; nj < 8; nj++)
                    MMA_TF32(acc[mi][nj], a0, a1, a2, a3, bf[nj][0], bf[nj][1]);
            }
        }

        if (it + 2 < NIT) {
            __syncthreads();                  // buffer it&1 fully consumed
            stage(it & 1, (it + 2) * 32);
        }
    }

    #pragma unroll
    for (int mi = 0; mi < 4; mi++) {
        #pragma unroll
        for (int nj = 0; nj < 8; nj++) {
            int row = m0 + wm * 64 + mi * 16 + g;
            int col = n0 + wn * 64 + nj * 8 + 2 * tig;
            float2 v0, v1;
            v0.x = acc[mi][nj][0]; v0.y = acc[mi][nj][1];
            v1.x = acc[mi][nj][2]; v1.y = acc[mi][nj][3];
            *(float2*)&Ce[(size_t)row * ND + col]       = v0;
            *(float2*)&Ce[(size_t)(row + 8) * ND + col] = v1;
        }
    }
}

extern "C" void kernel_launch(void* const* d_in, const int* in_sizes, int n_in,
                              void* d_out, int out_size)
{
    const float* x  = (const float*)d_in[0];
    const float* w1 = (const float*)d_in[1];
    const float* w2 = (const float*)d_in[2];
    const float* w3 = (const float*)d_in[3];
    float* out = (float*)d_out;

    float* s1 = nullptr;
    float* s2 = nullptr;
    cudaGetSymbolAddress((void**)&s1, g_s1);   // no allocation; capture-safe
    cudaGetSymbolAddress((void**)&s2, g_s2);

    constexpr size_t SMU = 3 * (size_t)(128 * 36 + 32 * 136) * sizeof(float);  // 107520
    constexpr size_t SMD = 2 * (size_t)(128 * 40 + 128 * 40) * sizeof(float);  // 81920
    cudaFuncSetAttribute(gemm_upgate<0>, cudaFuncAttributeMaxDynamicSharedMemorySize, SMU);
    cudaFuncSetAttribute(gemm_upgate<1>, cudaFuncAttributeMaxDynamicSharedMemorySize, SMU);
    cudaFuncSetAttribute(gemm_down,      cudaFuncAttributeMaxDynamicSharedMemorySize, SMD);

    dim3 blk(128);
    dim3 g0(NH / 128, NT / 128, NE);   // (64, 2, 8)
    dim3 g1(ND / 128, NT / 128, NE);   // (16, 2, 8)

    // 0) pre-round x to tf32 (A operand of GEMM1/2)
    int n4 = NE * NT * ND / 4;
    round_tf32<<<(n4 + 255) / 256, 256>>>(x, s2, n4);

    // 1) h1 = x @ w1                       -> s1
    gemm_upgate<0><<<g0, blk, SMU>>>(s2, w1, s1, s1);
    // 2) mid = round(silu(h1) * (x @ w3))  -> s1 (in place)
    gemm_upgate<1><<<g0, blk, SMU>>>(s2, w3, s1, s1);
    // 3) out = mid @ w2^T
    gemm_down<<<g1, blk, SMD>>>(s1, w2, out);
}

// round 16
// speedup vs baseline: 1.1108x; 1.0093x over previous
#include <cuda_runtime.h>
#include <math.h>

static constexpr int NE = 8;
static constexpr int NT = 256;
static constexpr int ND = 2048;
static constexpr int NH = 8192;

// Scratch (__device__ globals: allocation-guard safe)
__device__ float g_s1[(size_t)NE * NT * NH];   // h1 / mid (64MB)
__device__ float g_s2[(size_t)NE * NT * ND];   // tf32-rounded x (16MB)

__device__ __forceinline__ unsigned f2tf(float x) {
    unsigned r;
    asm("cvt.rna.tf32.f32 %0, %1;" : "=r"(r) : "f"(x));
    return r;
}

__device__ __forceinline__ float silu(float x) {
    return x / (1.0f + __expf(-x));
}

__device__ __forceinline__ unsigned s2u(const void* p) {
    unsigned a;
    asm("{ .reg .u64 t; cvta.to.shared.u64 t, %1; cvt.u32.u64 %0, t; }" : "=r"(a) : "l"(p));
    return a;
}

__device__ __forceinline__ void cpasync16(unsigned dst, const void* src) {
    asm volatile("cp.async.cg.shared.global [%0], [%1], 16;" :: "r"(dst), "l"(src) : "memory");
}

#define MMA_TF32(ACC, A0, A1, A2, A3, B0, B1)                                  \
    asm volatile(                                                              \
        "mma.sync.aligned.m16n8k8.row.col.f32.tf32.tf32.f32 "                  \
        "{%0,%1,%2,%3}, {%4,%5,%6,%7}, {%8,%9}, {%0,%1,%2,%3};"                \
        : "+f"((ACC)[0]), "+f"((ACC)[1]), "+f"((ACC)[2]), "+f"((ACC)[3])       \
        : "r"(A0), "r"(A1), "r"(A2), "r"(A3), "r"(B0), "r"(B1))

// Elementwise tf32 pre-round (x -> g_s2)
__global__ void round_tf32(const float* __restrict__ in, float* __restrict__ out, int n4) {
    int i = blockIdx.x * blockDim.x + threadIdx.x;
    if (i < n4) {
        float4 v = ((const float4*)in)[i];
        float4 w;
        w.x = __uint_as_float(f2tf(v.x));
        w.y = __uint_as_float(f2tf(v.y));
        w.z = __uint_as_float(f2tf(v.z));
        w.w = __uint_as_float(f2tf(v.w));
        ((float4*)out)[i] = w;
    }
}

// ---------------------------------------------------------------------------
// Up/gate GEMM (R8-measured-best, unchanged): C[NT,NH] = A[NT,ND] @ B[ND,NH]
// 256 threads, 8 warps 2x4, warp tile 64x32. SA=36 / SB=136, LDS.32 frags,
// 3-stage cp.async, 1 barrier/iter.
// EPI 0: C = acc      EPI 1: C = round(silu(Saux) * acc)
// ---------------------------------------------------------------------------
template<int EPI>
__global__ __launch_bounds__(256, 2)
void gemm_upgate(const float* __restrict__ A, const float* __restrict__ Bg,
                 const float* __restrict__ Saux, float* __restrict__ Cg)
{
    constexpr int SA = 36;            // frag bank 4g+tig -> conflict-free
    constexpr int SB = 136;           // frag bank 8tig+g -> conflict-free
    constexpr int ASZ = 128 * SA;
    constexpr int BSZ = 32 * SB;
    constexpr int STG = ASZ + BSZ;

    extern __shared__ float sm[];
    const unsigned sbase = s2u(sm);

    const int tid  = threadIdx.x;
    const int wid  = tid >> 5;
    const int lane = tid & 31;
    const int wm   = wid >> 2;
    const int wn   = wid & 3;
    const int g    = lane >> 2;
    const int tig  = lane & 3;

    const int m0 = blockIdx.y * 128;
    const int n0 = blockIdx.x * 128;
    const size_t z = blockIdx.z;

    const float* Ae = A  + z * (size_t)NT * ND + (size_t)m0 * ND;
    const float* Be = Bg + z * (size_t)ND * NH;
    float*       Ce = Cg + z * (size_t)NT * NH;
    const float* Se = Saux + z * (size_t)NT * NH;

    float acc[4][4][4];
    #pragma unroll
    for (int i = 0; i < 4; i++)
        #pragma unroll
        for (int j = 0; j < 4; j++)
            #pragma unroll
            for (int k = 0; k < 4; k++)
                acc[i][j][k] = 0.0f;

    auto stage = [&](int s, int kt) {
        const unsigned ab = sbase + (unsigned)s * STG * 4;
        const unsigned bb = ab + ASZ * 4;
        #pragma unroll
        for (int i = 0; i < 4; i++) {
            int idx = tid + i * 256;
            int r = idx >> 3, c = (idx & 7) * 4;
            cpasync16(ab + (r * SA + c) * 4, Ae + (size_t)r * ND + kt + c);
        }
        #pragma unroll
        for (int i = 0; i < 4; i++) {
            int idx = tid + i * 256;
            int kr = idx >> 5, nc = (idx & 31) * 4;
            cpasync16(bb + (kr * SB + nc) * 4, Be + (size_t)(kt + kr) * NH + n0 + nc);
        }
        asm volatile("cp.async.commit_group;" ::: "memory");
    };

    constexpr int NIT = ND / 32;      // 64
    stage(0, 0);
    stage(1, 32);

    #pragma unroll 1
    for (int it = 0; it < NIT; it++) {
        if (it + 1 < NIT) asm volatile("cp.async.wait_group 1;" ::: "memory");
        else              asm volatile("cp.async.wait_group 0;" ::: "memory");
        __syncthreads();
        if (it + 2 < NIT) stage((it + 2) % 3, (it + 2) * 32);

        const float* As = sm + (size_t)(it % 3) * STG;
        const float* Bs = As + ASZ;

        #pragma unroll
        for (int ks = 0; ks < 4; ks++) {
            const int k8 = ks * 8;

            unsigned af[4][4];
            #pragma unroll
            for (int mi = 0; mi < 4; mi++) {
                int row = wm * 64 + mi * 16 + g;
                af[mi][0] = __float_as_uint(As[row       * SA + k8 + tig]);
                af[mi][1] = __float_as_uint(As[(row + 8) * SA + k8 + tig]);
                af[mi][2] = __float_as_uint(As[row       * SA + k8 + tig + 4]);
                af[mi][3] = __float_as_uint(As[(row + 8) * SA + k8 + tig + 4]);
            }
            unsigned bf[4][2];
            #pragma unroll
            for (int nj = 0; nj < 4; nj++) {
                int n = wn * 32 + nj * 8 + g;
                bf[nj][0] = f2tf(Bs[(k8 + tig)     * SB + n]);
                bf[nj][1] = f2tf(Bs[(k8 + tig + 4) * SB + n]);
            }
            #pragma unroll
            for (int mi = 0; mi < 4; mi++) {
                #pragma unroll
                for (int nj = 0; nj < 4; nj++)
                    MMA_TF32(acc[mi][nj], af[mi][0], af[mi][1], af[mi][2], af[mi][3],
                             bf[nj][0], bf[nj][1]);
            }
        }
    }

    #pragma unroll
    for (int mi = 0; mi < 4; mi++) {
        #pragma unroll
        for (int nj = 0; nj < 4; nj++) {
            int row = m0 + wm * 64 + mi * 16 + g;
            int col = n0 + wn * 32 + nj * 8 + tig * 2;
            size_t i00 = (size_t)row * NH + col;
            size_t i10 = (size_t)(row + 8) * NH + col;
            float2 v0, v1;
            if (EPI == 0) {
                v0.x = acc[mi][nj][0]; v0.y = acc[mi][nj][1];
                v1.x = acc[mi][nj][2]; v1.y = acc[mi][nj][3];
            } else {
                float2 h0 = *(const float2*)&Se[i00];
                float2 h1 = *(const float2*)&Se[i10];
                // store mid tf32-rounded so gemm_down's A needs no cvt
                v0.x = __uint_as_float(f2tf(silu(h0.x) * acc[mi][nj][0]));
                v0.y = __uint_as_float(f2tf(silu(h0.y) * acc[mi][nj][1]));
                v1.x = __uint_as_float(f2tf(silu(h1.x) * acc[mi][nj][2]));
                v1.y = __uint_as_float(f2tf(silu(h1.y) * acc[mi][nj][3]));
            }
            *(float2*)&Ce[i00] = v0;
            *(float2*)&Ce[i10] = v1;
        }
    }
}

// ---------------------------------------------------------------------------
// Down proj (R15-measured-best, unchanged): out[T,D] = mid[T,H] @ w2[D,H]^T.
// 128 threads, 4 warps 2x2, warp tile 64x64. A pre-rounded; B k-contiguous.
// SA=SB=40, LDS.64 both operands via k-permutation. 2-stage cp.async.
// ---------------------------------------------------------------------------
__global__ __launch_bounds__(128, 2)
void gemm_down(const float* __restrict__ A, const float* __restrict__ Bg,
               float* __restrict__ Cg)
{
    constexpr int SA = 40;
    constexpr int SB = 40;            // banks 8g+2tig -> LDS.64 conflict-free
    constexpr int ASZ = 128 * SA;
    constexpr int BSZ = 128 * SB;
    constexpr int STG = ASZ + BSZ;

    extern __shared__ float sm[];
    const unsigned sbase = s2u(sm);

    const int tid  = threadIdx.x;
    const int wid  = tid >> 5;
    const int lane = tid & 31;
    const int wm   = wid >> 1;
    const int wn   = wid & 1;
    const int g    = lane >> 2;
    const int tig  = lane & 3;

    const int m0 = blockIdx.y * 128;
    const int n0 = blockIdx.x * 128;
    const size_t z = blockIdx.z;

    const float* Ae = A  + z * (size_t)NT * NH + (size_t)m0 * NH;
    const float* Be = Bg + z * (size_t)ND * NH;
    float*       Ce = Cg + z * (size_t)NT * ND;

    float acc[4][8][4];
    #pragma unroll
    for (int i = 0; i < 4; i++)
        #pragma unroll
        for (int j = 0; j < 8; j++)
            #pragma unroll
            for (int k = 0; k < 4; k++)
                acc[i][j][k] = 0.0f;

    auto stage = [&](int s, int kt) {
        const unsigned ab = sbase + (unsigned)s * STG * 4;
        const unsigned bb = ab + ASZ * 4;
        #pragma unroll
        for (int i = 0; i < 8; i++) {
            int idx = tid + i * 128;
            int r = idx >> 3, c = (idx & 7) * 4;
            cpasync16(ab + (r * SA + c) * 4, Ae + (size_t)r * NH + kt + c);
        }
        #pragma unroll
        for (int i = 0; i < 8; i++) {
            int idx = tid + i * 128;
            int nr = idx >> 3, kc = (idx & 7) * 4;
            cpasync16(bb + (nr * SB + kc) * 4, Be + (size_t)(n0 + nr) * NH + kt + kc);
        }
        asm volatile("cp.async.commit_group;" ::: "memory");
    };

    constexpr int NIT = NH / 32;      // 256
    stage(0, 0);
    stage(1, 32);

    #pragma unroll 1
    for (int it = 0; it < NIT; it++) {
        if (it + 1 < NIT) asm volatile("cp.async.wait_group 1;" ::: "memory");
        else              asm volatile("cp.async.wait_group 0;" ::: "memory");
        __syncthreads();

        const float* As = sm + (size_t)(it & 1) * STG;
        const float* Bs = As + ASZ;

        #pragma unroll
        for (int ks = 0; ks < 4; ks++) {
            const int kk = ks * 8 + 2 * tig;

            float2 a[4][2];
            #pragma unroll
            for (int mi = 0; mi < 4; mi++) {
                int row = wm * 64 + mi * 16 + g;
                a[mi][0] = *(const float2*)&As[row       * SA + kk];
                a[mi][1] = *(const float2*)&As[(row + 8) * SA + kk];
            }
            unsigned bf[8][2];
            #pragma unroll
            for (int nj = 0; nj < 8; nj++) {
                int n = wn * 64 + nj * 8 + g;
                float2 bp = *(const float2*)&Bs[n * SB + kk];
                bf[nj][0] = f2tf(bp.x);
                bf[nj][1] = f2tf(bp.y);
            }
            #pragma unroll
            for (int mi = 0; mi < 4; mi++) {
                unsigned a0 = __float_as_uint(a[mi][0].x);
                unsigned a1 = __float_as_uint(a[mi][1].x);
                unsigned a2 = __float_as_uint(a[mi][0].y);
                unsigned a3 = __float_as_uint(a[mi][1].y);
                #pragma unroll
                for (int nj = 0; nj < 8; nj++)
                    MMA_TF32(acc[mi][nj], a0, a1, a2, a3, bf[nj][0], bf[nj][1]);
            }
        }

        if (it + 2 < NIT) {
            __syncthreads();                  // buffer it&1 fully consumed
            stage(it & 1, (it + 2) * 32);
        }
    }

    #pragma unroll
    for (int mi = 0; mi < 4; mi++) {
        #pragma unroll
        for (int nj = 0; nj < 8; nj++) {
            int row = m0 + wm * 64 + mi * 16 + g;
            int col = n0 + wn * 64 + nj * 8 + 2 * tig;
            float2 v0, v1;
            v0.x = acc[mi][nj][0]; v0.y = acc[mi][nj][1];
            v1.x = acc[mi][nj][2]; v1.y = acc[mi][nj][3];
            *(float2*)&Ce[(size_t)row * ND + col]       = v0;
            *(float2*)&Ce[(size_t)(row + 8) * ND + col] = v1;
        }
    }
}

extern "C" void kernel_launch(void* const* d_in, const int* in_sizes, int n_in,
                              void* d_out, int out_size)
{
    const float* x  = (const float*)d_in[0];
    const float* w1 = (const float*)d_in[1];
    const float* w2 = (const float*)d_in[2];
    const float* w3 = (const float*)d_in[3];
    float* out = (float*)d_out;

    float* s1 = nullptr;
    float* s2 = nullptr;
    cudaGetSymbolAddress((void**)&s1, g_s1);   // no allocation; capture-safe
    cudaGetSymbolAddress((void**)&s2, g_s2);

    constexpr size_t SMU = 3 * (size_t)(128 * 36 + 32 * 136) * sizeof(float);  // 107520
    constexpr size_t SMD = 2 * (size_t)(128 * 40 + 128 * 40) * sizeof(float);  // 81920
    cudaFuncSetAttribute(gemm_upgate<0>, cudaFuncAttributeMaxDynamicSharedMemorySize, SMU);
    cudaFuncSetAttribute(gemm_upgate<1>, cudaFuncAttributeMaxDynamicSharedMemorySize, SMU);
    cudaFuncSetAttribute(gemm_down,      cudaFuncAttributeMaxDynamicSharedMemorySize, SMD);

    dim3 g0(NH / 128, NT / 128, NE);   // (64, 2, 8)
    dim3 g1(ND / 128, NT / 128, NE);   // (16, 2, 8)

    // 0) pre-round x to tf32 (A operand of GEMM1/2)
    int n4 = NE * NT * ND / 4;
    round_tf32<<<(n4 + 255) / 256, 256>>>(x, s2, n4);

    // 1) h1 = x @ w1                       -> s1
    gemm_upgate<0><<<g0, dim3(256), SMU>>>(s2, w1, s1, s1);
    // 2) mid = round(silu(h1) * (x @ w3))  -> s1 (in place)
    gemm_upgate<1><<<g0, dim3(256), SMU>>>(s2, w3, s1, s1);
    // 3) out = mid @ w2^T
    gemm_down<<<g1, dim3(128), SMD>>>(s1, w2, out);
}

// round 17
// speedup vs baseline: 1.1898x; 1.0711x over previous
#include <cuda_runtime.h>
#include <math.h>

static constexpr int NE = 8;
static constexpr int NT = 256;
static constexpr int ND = 2048;
static constexpr int NH = 8192;

// Scratch (__device__ globals: allocation-guard safe)
__device__ float g_s1[(size_t)NE * NT * NH];   // mid (64MB)
__device__ float g_s2[(size_t)NE * NT * ND];   // tf32-rounded x (16MB)

__device__ __forceinline__ unsigned f2tf(float x) {
    unsigned r;
    asm("cvt.rna.tf32.f32 %0, %1;" : "=r"(r) : "f"(x));
    return r;
}

__device__ __forceinline__ float silu(float x) {
    return x / (1.0f + __expf(-x));
}

__device__ __forceinline__ unsigned s2u(const void* p) {
    unsigned a;
    asm("{ .reg .u64 t; cvta.to.shared.u64 t, %1; cvt.u32.u64 %0, t; }" : "=r"(a) : "l"(p));
    return a;
}

__device__ __forceinline__ void cpasync16(unsigned dst, const void* src) {
    asm volatile("cp.async.cg.shared.global [%0], [%1], 16;" :: "r"(dst), "l"(src) : "memory");
}

#define MMA_TF32(ACC, A0, A1, A2, A3, B0, B1)                                  \
    asm volatile(                                                              \
        "mma.sync.aligned.m16n8k8.row.col.f32.tf32.tf32.f32 "                  \
        "{%0,%1,%2,%3}, {%4,%5,%6,%7}, {%8,%9}, {%0,%1,%2,%3};"                \
        : "+f"((ACC)[0]), "+f"((ACC)[1]), "+f"((ACC)[2]), "+f"((ACC)[3])       \
        : "r"(A0), "r"(A1), "r"(A2), "r"(A3), "r"(B0), "r"(B1))

// Elementwise tf32 pre-round (x -> g_s2)
__global__ void round_tf32(const float* __restrict__ in, float* __restrict__ out, int n4) {
    int i = blockIdx.x * blockDim.x + threadIdx.x;
    if (i < n4) {
        float4 v = ((const float4*)in)[i];
        float4 w;
        w.x = __uint_as_float(f2tf(v.x));
        w.y = __uint_as_float(f2tf(v.y));
        w.z = __uint_as_float(f2tf(v.z));
        w.w = __uint_as_float(f2tf(v.w));
        ((float4*)out)[i] = w;
    }
}

// ---------------------------------------------------------------------------
// Fused up+gate: mid = round_tf32( silu(x@w1) * (x@w3) )   -> g_s1
// A = pre-rounded x [NT,ND]; W1/W3 [ND,NH] n-contiguous.
// CTA tile 128x128 (BN=128: full weight reuse, unlike the failed R10 BN=64).
// 256 threads, 8 warps 2x4, warp tile 64x32 PER OUTPUT -> acc1+acc3 = 128 regs.
// launch_bounds(256,1): ~200 regs OK, 3-stage x 53.2KB = 159.7KB smem, 1 CTA/SM
// (= 2 warps/SMSP, the operating point gemm_down proves works).
// Memory scheme per stage = R8-proven: SA=36 (bank 4g+tig), SB=136 (bank 8tig+g).
// Per k8: 32 LDS + 16 cvt for 32 MMAs = 1.5 issues/MMA (was 3.0).
// ---------------------------------------------------------------------------
__global__ __launch_bounds__(256, 1)
void ffn_fused(const float* __restrict__ A, const float* __restrict__ W1,
               const float* __restrict__ W3, float* __restrict__ Cg)
{
    constexpr int SA = 36;
    constexpr int SB = 136;
    constexpr int ASZ = 128 * SA;
    constexpr int BSZ = 32 * SB;
    constexpr int STG = ASZ + 2 * BSZ;     // 13312 floats = 53248 B

    extern __shared__ float sm[];
    const unsigned sbase = s2u(sm);

    const int tid  = threadIdx.x;
    const int wid  = tid >> 5;
    const int lane = tid & 31;
    const int wm   = wid >> 2;       // 0..1
    const int wn   = wid & 3;        // 0..3
    const int g    = lane >> 2;
    const int tig  = lane & 3;

    const int m0 = blockIdx.y * 128;
    const int n0 = blockIdx.x * 128;
    const size_t z = blockIdx.z;

    const float* Ae  = A  + z * (size_t)NT * ND + (size_t)m0 * ND;
    const float* B1e = W1 + z * (size_t)ND * NH;
    const float* B3e = W3 + z * (size_t)ND * NH;
    float*       Ce  = Cg + z * (size_t)NT * NH;

    float acc1[4][4][4], acc3[4][4][4];
    #pragma unroll
    for (int i = 0; i < 4; i++)
        #pragma unroll
        for (int j = 0; j < 4; j++)
            #pragma unroll
            for (int k = 0; k < 4; k++) { acc1[i][j][k] = 0.0f; acc3[i][j][k] = 0.0f; }

    auto stage = [&](int s, int kt) {
        const unsigned ab = sbase + (unsigned)s * STG * 4;
        const unsigned b1 = ab + ASZ * 4;
        const unsigned b3 = b1 + BSZ * 4;
        #pragma unroll
        for (int i = 0; i < 4; i++) {
            int idx = tid + i * 256;
            int r = idx >> 3, c = (idx & 7) * 4;
            cpasync16(ab + (r * SA + c) * 4, Ae + (size_t)r * ND + kt + c);
        }
        #pragma unroll
        for (int i = 0; i < 4; i++) {
            int idx = tid + i * 256;
            int kr = idx >> 5, nc = (idx & 31) * 4;
            cpasync16(b1 + (kr * SB + nc) * 4, B1e + (size_t)(kt + kr) * NH + n0 + nc);
            cpasync16(b3 + (kr * SB + nc) * 4, B3e + (size_t)(kt + kr) * NH + n0 + nc);
        }
        asm volatile("cp.async.commit_group;" ::: "memory");
    };

    constexpr int NIT = ND / 32;      // 64
    stage(0, 0);
    stage(1, 32);

    #pragma unroll 1
    for (int it = 0; it < NIT; it++) {
        if (it + 1 < NIT) asm volatile("cp.async.wait_group 1;" ::: "memory");
        else              asm volatile("cp.async.wait_group 0;" ::: "memory");
        __syncthreads();
        if (it + 2 < NIT) stage((it + 2) % 3, (it + 2) * 32);

        const float* As  = sm + (size_t)(it % 3) * STG;
        const float* B1s = As + ASZ;
        const float* B3s = B1s + BSZ;

        #pragma unroll
        for (int ks = 0; ks < 4; ks++) {
            const int k8 = ks * 8;

            unsigned af[4][4];
            #pragma unroll
            for (int mi = 0; mi < 4; mi++) {
                int row = wm * 64 + mi * 16 + g;
                af[mi][0] = __float_as_uint(As[row       * SA + k8 + tig]);
                af[mi][1] = __float_as_uint(As[(row + 8) * SA + k8 + tig]);
                af[mi][2] = __float_as_uint(As[row       * SA + k8 + tig + 4]);
                af[mi][3] = __float_as_uint(As[(row + 8) * SA + k8 + tig + 4]);
            }
            unsigned b1f[4][2], b3f[4][2];
            #pragma unroll
            for (int nj = 0; nj < 4; nj++) {
                int n = wn * 32 + nj * 8 + g;
                b1f[nj][0] = f2tf(B1s[(k8 + tig)     * SB + n]);
                b1f[nj][1] = f2tf(B1s[(k8 + tig + 4) * SB + n]);
                b3f[nj][0] = f2tf(B3s[(k8 + tig)     * SB + n]);
                b3f[nj][1] = f2tf(B3s[(k8 + tig + 4) * SB + n]);
            }
            #pragma unroll
            for (int mi = 0; mi < 4; mi++) {
                #pragma unroll
                for (int nj = 0; nj < 4; nj++) {
                    MMA_TF32(acc1[mi][nj], af[mi][0], af[mi][1], af[mi][2], af[mi][3],
                             b1f[nj][0], b1f[nj][1]);
                    MMA_TF32(acc3[mi][nj], af[mi][0], af[mi][1], af[mi][2], af[mi][3],
                             b3f[nj][0], b3f[nj][1]);
                }
            }
        }
    }

    // epilogue: mid = round(silu(h1) * h3)  (tf32-rounded for gemm_down's A)
    #pragma unroll
    for (int mi = 0; mi < 4; mi++) {
        #pragma unroll
        for (int nj = 0; nj < 4; nj++) {
            int row = m0 + wm * 64 + mi * 16 + g;
            int col = n0 + wn * 32 + nj * 8 + tig * 2;
            size_t i00 = (size_t)row * NH + col;
            size_t i10 = (size_t)(row + 8) * NH + col;
            float2 v0, v1;
            v0.x = __uint_as_float(f2tf(silu(acc1[mi][nj][0]) * acc3[mi][nj][0]));
            v0.y = __uint_as_float(f2tf(silu(acc1[mi][nj][1]) * acc3[mi][nj][1]));
            v1.x = __uint_as_float(f2tf(silu(acc1[mi][nj][2]) * acc3[mi][nj][2]));
            v1.y = __uint_as_float(f2tf(silu(acc1[mi][nj][3]) * acc3[mi][nj][3]));
            *(float2*)&Ce[i00] = v0;
            *(float2*)&Ce[i10] = v1;
        }
    }
}

// ---------------------------------------------------------------------------
// Down proj (R15/R16-measured-best, unchanged): out[T,D] = mid[T,H] @ w2^T.
// 128 threads, 4 warps 2x2, warp tile 64x64. A pre-rounded; B k-contiguous.
// SA=SB=40, LDS.64 both operands via k-permutation (physical slot tig <-
// logical k8+2tig, slot tig+4 <- k8+2tig+1, same bijection on A and B).
// 2-stage cp.async.
// ---------------------------------------------------------------------------
__global__ __launch_bounds__(128, 2)
void gemm_down(const float* __restrict__ A, const float* __restrict__ Bg,
               float* __restrict__ Cg)
{
    constexpr int SA = 40;
    constexpr int SB = 40;            // banks 8g+2tig -> LDS.64 conflict-free
    constexpr int ASZ = 128 * SA;
    constexpr int BSZ = 128 * SB;
    constexpr int STG = ASZ + BSZ;

    extern __shared__ float sm[];
    const unsigned sbase = s2u(sm);

    const int tid  = threadIdx.x;
    const int wid  = tid >> 5;
    const int lane = tid & 31;
    const int wm   = wid >> 1;
    const int wn   = wid & 1;
    const int g    = lane >> 2;
    const int tig  = lane & 3;

    const int m0 = blockIdx.y * 128;
    const int n0 = blockIdx.x * 128;
    const size_t z = blockIdx.z;

    const float* Ae = A  + z * (size_t)NT * NH + (size_t)m0 * NH;
    const float* Be = Bg + z * (size_t)ND * NH;
    float*       Ce = Cg + z * (size_t)NT * ND;

    float acc[4][8][4];
    #pragma unroll
    for (int i = 0; i < 4; i++)
        #pragma unroll
        for (int j = 0; j < 8; j++)
            #pragma unroll
            for (int k = 0; k < 4; k++)
                acc[i][j][k] = 0.0f;

    auto stage = [&](int s, int kt) {
        const unsigned ab = sbase + (unsigned)s * STG * 4;
        const unsigned bb = ab + ASZ * 4;
        #pragma unroll
        for (int i = 0; i < 8; i++) {
            int idx = tid + i * 128;
            int r = idx >> 3, c = (idx & 7) * 4;
            cpasync16(ab + (r * SA + c) * 4, Ae + (size_t)r * NH + kt + c);
        }
        #pragma unroll
        for (int i = 0; i < 8; i++) {
            int idx = tid + i * 128;
            int nr = idx >> 3, kc = (idx & 7) * 4;
            cpasync16(bb + (nr * SB + kc) * 4, Be + (size_t)(n0 + nr) * NH + kt + kc);
        }
        asm volatile("cp.async.commit_group;" ::: "memory");
    };

    constexpr int NIT = NH / 32;      // 256
    stage(0, 0);
    stage(1, 32);

    #pragma unroll 1
    for (int it = 0; it < NIT; it++) {
        if (it + 1 < NIT) asm volatile("cp.async.wait_group 1;" ::: "memory");
        else              asm volatile("cp.async.wait_group 0;" ::: "memory");
        __syncthreads();

        const float* As = sm + (size_t)(it & 1) * STG;
        const float* Bs = As + ASZ;

        #pragma unroll
        for (int ks = 0; ks < 4; ks++) {
            const int kk = ks * 8 + 2 * tig;

            float2 a[4][2];
            #pragma unroll
            for (int mi = 0; mi < 4; mi++) {
                int row = wm * 64 + mi * 16 + g;
                a[mi][0] = *(const float2*)&As[row       * SA + kk];
                a[mi][1] = *(const float2*)&As[(row + 8) * SA + kk];
            }
            unsigned bf[8][2];
            #pragma unroll
            for (int nj = 0; nj < 8; nj++) {
                int n = wn * 64 + nj * 8 + g;
                float2 bp = *(const float2*)&Bs[n * SB + kk];
                bf[nj][0] = f2tf(bp.x);
                bf[nj][1] = f2tf(bp.y);
            }
            #pragma unroll
            for (int mi = 0; mi < 4; mi++) {
                unsigned a0 = __float_as_uint(a[mi][0].x);
                unsigned a1 = __float_as_uint(a[mi][1].x);
                unsigned a2 = __float_as_uint(a[mi][0].y);
                unsigned a3 = __float_as_uint(a[mi][1].y);
                #pragma unroll
                for (int nj = 0; nj < 8; nj++)
                    MMA_TF32(acc[mi][nj], a0, a1, a2, a3, bf[nj][0], bf[nj][1]);
            }
        }

        if (it + 2 < NIT) {
            __syncthreads();                  // buffer it&1 fully consumed
            stage(it & 1, (it + 2) * 32);
        }
    }

    #pragma unroll
    for (int mi = 0; mi < 4; mi++) {
        #pragma unroll
        for (int nj = 0; nj < 8; nj++) {
            int row = m0 + wm * 64 + mi * 16 + g;
            int col = n0 + wn * 64 + nj * 8 + 2 * tig;
            float2 v0, v1;
            v0.x = acc[mi][nj][0]; v0.y = acc[mi][nj][1];
            v1.x = acc[mi][nj][2]; v1.y = acc[mi][nj][3];
            *(float2*)&Ce[(size_t)row * ND + col]       = v0;
            *(float2*)&Ce[(size_t)(row + 8) * ND + col] = v1;
        }
    }
}

extern "C" void kernel_launch(void* const* d_in, const int* in_sizes, int n_in,
                              void* d_out, int out_size)
{
    const float* x  = (const float*)d_in[0];
    const float* w1 = (const float*)d_in[1];
    const float* w2 = (const float*)d_in[2];
    const float* w3 = (const float*)d_in[3];
    float* out = (float*)d_out;

    float* s1 = nullptr;
    float* s2 = nullptr;
    cudaGetSymbolAddress((void**)&s1, g_s1);   // no allocation; capture-safe
    cudaGetSymbolAddress((void**)&s2, g_s2);

    constexpr size_t SMF = 3 * (size_t)(128 * 36 + 2 * 32 * 136) * sizeof(float); // 159744
    constexpr size_t SMD = 2 * (size_t)(128 * 40 + 128 * 40) * sizeof(float);     // 81920
    cudaFuncSetAttribute(ffn_fused, cudaFuncAttributeMaxDynamicSharedMemorySize, SMF);
    cudaFuncSetAttribute(gemm_down, cudaFuncAttributeMaxDynamicSharedMemorySize, SMD);

    dim3 gf(NH / 128, NT / 128, NE);   // (64, 2, 8)
    dim3 gd(ND / 128, NT / 128, NE);   // (16, 2, 8)

    // 0) pre-round x to tf32 (A operand of the fused kernel)
    int n4 = NE * NT * ND / 4;
    round_tf32<<<(n4 + 255) / 256, 256>>>(x, s2, n4);

    // 1) mid = round(silu(x@w1) * (x@w3))  -> s1   (h1 never hits DRAM)
    ffn_fused<<<gf, dim3(256), SMF>>>(s2, w1, w3, s1);

    // 2) out = mid @ w2^T
    gemm_down<<<gd, dim3(128), SMD>>>(s1, w2, out);
}